// round 4
// baseline (speedup 1.0000x reference)
#include <cuda_runtime.h>
#include <cstdint>
#include <math.h>

#define SEQ 2048
#define EMB 1024
#define NBQ 256
#define NH 16
#define HD 64
#define NBATCH 2
#define NROWS (NBATCH*SEQ)   // 4096
#define NKT (SEQ/64)         // 32 kv tiles
#define NQT (SEQ/128)        // 16 q tiles

// ---------------- scratch (device globals) ---------------------------------
__device__ float g_Wq[EMB*EMB];
__device__ float g_Wk[EMB*EMB];
__device__ float g_Wv[EMB*EMB];
__device__ float g_Wo[EMB*EMB];
__device__ float g_Q[NROWS*EMB];
__device__ float g_K[NROWS*EMB];
__device__ float g_V[NROWS*EMB];
__device__ float g_ctx[NROWS*EMB];
__device__ int   g_msum[NQT*NKT];

// ---------------- helpers ---------------------------------------------------
__device__ __forceinline__ unsigned f2tf32(float x) {
    unsigned u;
    asm("cvt.rna.tf32.f32 %0, %1;" : "=r"(u) : "f"(x));
    return u;
}
__device__ __forceinline__ float tf32f(float x) { return __uint_as_float(f2tf32(x)); }

__device__ __forceinline__ void mma_tf32(float* d, const unsigned* a, const unsigned* b) {
    asm volatile(
        "mma.sync.aligned.m16n8k8.row.col.f32.tf32.tf32.f32 "
        "{%0,%1,%2,%3},{%4,%5,%6,%7},{%8,%9},{%0,%1,%2,%3};"
        : "+f"(d[0]), "+f"(d[1]), "+f"(d[2]), "+f"(d[3])
        : "r"(a[0]), "r"(a[1]), "r"(a[2]), "r"(a[3]), "r"(b[0]), "r"(b[1]));
}

__device__ __forceinline__ uint32_t sa(const void* p) {
    return (uint32_t)__cvta_generic_to_shared(p);
}
__device__ __forceinline__ void cpa16(uint32_t s, const void* g) {
    asm volatile("cp.async.cg.shared.global [%0], [%1], 16;" :: "r"(s), "l"(g));
}
__device__ __forceinline__ void cp_commit() {
    asm volatile("cp.async.commit_group;" ::: "memory");
}
__device__ __forceinline__ void cp_wait0() {
    asm volatile("cp.async.wait_group 0;" ::: "memory");
}

// ---------------- weight expansion (quaternion left-mult), 4-in-1 ----------
struct Exp4 { const float* W[4]; float* Wb[4]; };

__global__ void expand4_kernel(Exp4 e) {
    int z = blockIdx.y;
    int idx = blockIdx.x * blockDim.x + threadIdx.x;
    if (idx >= NBQ * NBQ) return;
    int o = idx / NBQ;
    int n = idx % NBQ;
    const float* w = e.W[z] + (o * NBQ + n) * 4;
    float w0 = tf32f(w[0]), w1 = tf32f(w[1]), w2 = tf32f(w[2]), w3 = tf32f(w[3]);
    float* base = e.Wb[z] + (n * 4) * EMB + o * 4;
    *(float4*)(base + 0 * EMB) = make_float4( w0,  w1,  w2,  w3);
    *(float4*)(base + 1 * EMB) = make_float4(-w1,  w0,  w3, -w2);
    *(float4*)(base + 2 * EMB) = make_float4(-w2, -w3,  w0,  w1);
    *(float4*)(base + 3 * EMB) = make_float4(-w3,  w2, -w1,  w0);
}

// ---------------- mask tile summary (128q x 64k tiles) ----------------------
__global__ void mask_summary(const int* __restrict__ mask, int* __restrict__ sum) {
    int tile = blockIdx.x;
    int qt = tile / NKT, kt = tile % NKT;
    int tid = threadIdx.x;
    int ok = 1;
    for (int i = tid; i < 128*64; i += 256) {
        int r = i / 64, c = i % 64;
        ok &= (mask[(qt*128 + r) * SEQ + kt*64 + c] != 0);
    }
    int allok = __syncthreads_and(ok);
    if (tid == 0) sum[tile] = allok;
}

// ---------------- TF32 tensor-core GEMM (double-buffered) -------------------
#define ASTR 36
#define BSTR 136

struct GemmArgs {
    const float* A;
    const float* W[3];
    const float* bias[3];
    float* out[3];
    float oscale[3];
    int round_out;
};

__global__ __launch_bounds__(256) void gemm_tf32(GemmArgs ga) {
    extern __shared__ float gs[];
    float* Asm = gs;                       // 2 * 128*ASTR
    float* Bsm = gs + 2 * 128 * ASTR;      // 2 * 32*BSTR

    int tid = threadIdx.x;
    int z = blockIdx.z;
    const float* A = ga.A;
    const float* W = ga.W[z];
    const float* bias = ga.bias[z];
    float* C = ga.out[z];

    int bm = blockIdx.y * 128;
    int bn = blockIdx.x * 128;
    int warp = tid / 32, lane = tid % 32;
    int gid = lane >> 2, tig = lane & 3;
    int wm = (warp / 4) * 64, wn = (warp % 4) * 32;

    int arow = tid / 8;
    int acol = (tid % 8) * 4;
    int brow = tid / 32;
    int bcol = (tid % 32) * 4;

    float acc[4][4][4];
#pragma unroll
    for (int mt = 0; mt < 4; mt++)
#pragma unroll
        for (int nt = 0; nt < 4; nt++)
#pragma unroll
            for (int r = 0; r < 4; r++) acc[mt][nt][r] = 0.0f;

    float4 pa[4], pb[4];

#define LOADG(k0)                                                              \
    {                                                                          \
        _Pragma("unroll")                                                      \
        for (int i = 0; i < 4; i++)                                            \
            pa[i] = *(const float4*)(A + (long)(bm + arow + i*32) * EMB + (k0) + acol); \
        _Pragma("unroll")                                                      \
        for (int i = 0; i < 4; i++)                                            \
            pb[i] = *(const float4*)(W + (long)((k0) + brow + i*8) * EMB + bn + bcol);  \
    }
#define STORES(asb, bsb)                                                       \
    {                                                                          \
        _Pragma("unroll")                                                      \
        for (int i = 0; i < 4; i++) {                                          \
            int r = arow + i*32;                                               \
            (asb)[r*ASTR + acol + 0] = tf32f(pa[i].x);                         \
            (asb)[r*ASTR + acol + 1] = tf32f(pa[i].y);                         \
            (asb)[r*ASTR + acol + 2] = tf32f(pa[i].z);                         \
            (asb)[r*ASTR + acol + 3] = tf32f(pa[i].w);                         \
        }                                                                      \
        _Pragma("unroll")                                                      \
        for (int i = 0; i < 4; i++) {                                          \
            int r = brow + i*8;                                                \
            (bsb)[r*BSTR + bcol + 0] = tf32f(pb[i].x);                         \
            (bsb)[r*BSTR + bcol + 1] = tf32f(pb[i].y);                         \
            (bsb)[r*BSTR + bcol + 2] = tf32f(pb[i].z);                         \
            (bsb)[r*BSTR + bcol + 3] = tf32f(pb[i].w);                         \
        }                                                                      \
    }

    LOADG(0);
    STORES(Asm, Bsm);
    __syncthreads();

    for (int kt = 0; kt < EMB / 32; kt++) {
        if (kt + 1 < EMB / 32) LOADG((kt + 1) * 32);

        const float* As = Asm + (kt & 1) * 128 * ASTR;
        const float* Bs = Bsm + (kt & 1) * 32 * BSTR;
#pragma unroll
        for (int ks = 0; ks < 4; ks++) {
            int k0 = ks * 8;
            unsigned af[4][4], bf[4][2];
#pragma unroll
            for (int mt = 0; mt < 4; mt++) {
                int r0 = wm + mt * 16;
                af[mt][0] = __float_as_uint(As[(r0 + gid)     * ASTR + k0 + tig]);
                af[mt][1] = __float_as_uint(As[(r0 + gid + 8) * ASTR + k0 + tig]);
                af[mt][2] = __float_as_uint(As[(r0 + gid)     * ASTR + k0 + tig + 4]);
                af[mt][3] = __float_as_uint(As[(r0 + gid + 8) * ASTR + k0 + tig + 4]);
            }
#pragma unroll
            for (int nt = 0; nt < 4; nt++) {
                int c0 = wn + nt * 8;
                bf[nt][0] = __float_as_uint(Bs[(k0 + tig)     * BSTR + c0 + gid]);
                bf[nt][1] = __float_as_uint(Bs[(k0 + tig + 4) * BSTR + c0 + gid]);
            }
#pragma unroll
            for (int mt = 0; mt < 4; mt++)
#pragma unroll
                for (int nt = 0; nt < 4; nt++)
                    mma_tf32(acc[mt][nt], af[mt], bf[nt]);
        }
        if (kt + 1 < EMB / 32) {
            STORES(Asm + ((kt + 1) & 1) * 128 * ASTR,
                   Bsm + ((kt + 1) & 1) * 32 * BSTR);
            __syncthreads();
        }
    }

    float os = ga.oscale[z];
    int rnd = ga.round_out;
#pragma unroll
    for (int mt = 0; mt < 4; mt++)
#pragma unroll
        for (int nt = 0; nt < 4; nt++) {
            int gm = bm + wm + mt * 16 + gid;
            int gn = bn + wn + nt * 8 + tig * 2;
            float b0 = bias[gn], b1 = bias[gn + 1];
            float v0 = (acc[mt][nt][0] + b0) * os;
            float v1 = (acc[mt][nt][1] + b1) * os;
            float v2 = (acc[mt][nt][2] + b0) * os;
            float v3 = (acc[mt][nt][3] + b1) * os;
            if (rnd) { v0 = tf32f(v0); v1 = tf32f(v1); v2 = tf32f(v2); v3 = tf32f(v3); }
            *(float2*)(C + (long)gm * EMB + gn) = make_float2(v0, v1);
            *(float2*)(C + (long)(gm + 8) * EMB + gn) = make_float2(v2, v3);
        }
}

// ---------------- TF32 flash attention (BQ=128, cp.async double buffer) -----
#define BQ 128
#define BKV 64
#define QSTR 68
#define KSTR 68
#define VSTR 72
#define PSTR 72

__global__ __launch_bounds__(256) void flash_tf32(
    const float* __restrict__ Q, const float* __restrict__ K,
    const float* __restrict__ V, const int* __restrict__ mask,
    const int* __restrict__ msum, float* __restrict__ ctx)
{
    extern __shared__ float fs[];
    float* Qs = fs;                         // BQ*QSTR          = 8704
    float* Ks = Qs + BQ * QSTR;             // 2*BKV*KSTR       = 8704
    float* Vs = Ks + 2 * BKV * KSTR;        // 2*BKV*VSTR       = 9216
    float* Ps = Vs + 2 * BKV * VSTR;        // 8*16*PSTR        = 9216

    int tid = threadIdx.x;
    int w = tid / 32, lane = tid % 32;
    int gid = lane >> 2, tig = lane & 3;
    int qt = blockIdx.x, h = blockIdx.y, b = blockIdx.z;
    int q0 = qt * BQ;

    // Q tile via cp.async (values already tf32-rounded + pre-scaled by GEMM)
    {
        int row = tid >> 1;
        int c0 = (tid & 1) * 32;
        const float* g = Q + (long)(b * SEQ + q0 + row) * EMB + h * HD + c0;
        uint32_t s = sa(Qs + row * QSTR + c0);
#pragma unroll
        for (int j = 0; j < 8; j++) cpa16(s + j * 16, g + j * 4);
    }
    // K/V tile 0 into buffer 0
    {
        int row = tid >> 2;
        int c0 = (tid & 3) * 16;
        long gr = (long)(b * SEQ + row) * EMB + h * HD + c0;
        uint32_t ks = sa(Ks + row * KSTR + c0);
        uint32_t vs = sa(Vs + row * VSTR + c0);
#pragma unroll
        for (int j = 0; j < 4; j++) cpa16(ks + j * 16, K + gr + j * 4);
#pragma unroll
        for (int j = 0; j < 4; j++) cpa16(vs + j * 16, V + gr + j * 4);
    }
    cp_commit();
    cp_wait0();
    __syncthreads();

    // hoist Q fragments
    unsigned aq[8][4];
#pragma unroll
    for (int ks = 0; ks < 8; ks++) {
        int r0 = w * 16;
        int k0 = ks * 8;
        aq[ks][0] = __float_as_uint(Qs[(r0 + gid)     * QSTR + k0 + tig]);
        aq[ks][1] = __float_as_uint(Qs[(r0 + gid + 8) * QSTR + k0 + tig]);
        aq[ks][2] = __float_as_uint(Qs[(r0 + gid)     * QSTR + k0 + tig + 4]);
        aq[ks][3] = __float_as_uint(Qs[(r0 + gid + 8) * QSTR + k0 + tig + 4]);
    }

    float o[8][4];
#pragma unroll
    for (int dt = 0; dt < 8; dt++)
#pragma unroll
        for (int r = 0; r < 4; r++) o[dt][r] = 0.0f;
    float mA = -1e30f, mB = -1e30f, lA = 0.0f, lB = 0.0f;

    for (int kt = 0; kt < NKT; kt++) {
        // prefetch next K/V tile into the other buffer
        if (kt + 1 < NKT) {
            int nb = (kt + 1) & 1;
            int row = tid >> 2;
            int c0 = (tid & 3) * 16;
            long gr = (long)(b * SEQ + (kt + 1) * BKV + row) * EMB + h * HD + c0;
            uint32_t ks = sa(Ks + nb * BKV * KSTR + row * KSTR + c0);
            uint32_t vs = sa(Vs + nb * BKV * VSTR + row * VSTR + c0);
#pragma unroll
            for (int j = 0; j < 4; j++) cpa16(ks + j * 16, K + gr + j * 4);
#pragma unroll
            for (int j = 0; j < 4; j++) cpa16(vs + j * 16, V + gr + j * 4);
            cp_commit();
        }

        const float* Kb = Ks + (kt & 1) * BKV * KSTR;
        const float* Vb = Vs + (kt & 1) * BKV * VSTR;

        // S = Q K^T
        float s[8][4];
#pragma unroll
        for (int nt = 0; nt < 8; nt++) {
            s[nt][0] = s[nt][1] = s[nt][2] = s[nt][3] = 0.0f;
#pragma unroll
            for (int ks = 0; ks < 8; ks++) {
                int k0 = ks * 8;
                unsigned bk[2];
                bk[0] = __float_as_uint(Kb[(nt * 8 + gid) * KSTR + k0 + tig]);
                bk[1] = __float_as_uint(Kb[(nt * 8 + gid) * KSTR + k0 + tig + 4]);
                mma_tf32(s[nt], aq[ks], bk);
            }
        }

        // mask (only when tile contains zeros)
        if (!msum[qt * NKT + kt]) {
            int qrA = q0 + w * 16 + gid;
            int qrB = qrA + 8;
#pragma unroll
            for (int nt = 0; nt < 8; nt++) {
                int kc = kt * 64 + nt * 8 + tig * 2;
                const int* mpA = mask + (long)qrA * SEQ + kc;
                const int* mpB = mask + (long)qrB * SEQ + kc;
                if (mpA[0] == 0) s[nt][0] = -1e30f;
                if (mpA[1] == 0) s[nt][1] = -1e30f;
                if (mpB[0] == 0) s[nt][2] = -1e30f;
                if (mpB[1] == 0) s[nt][3] = -1e30f;
            }
        }

        // online softmax
        float mxA = -1e30f, mxB = -1e30f;
#pragma unroll
        for (int nt = 0; nt < 8; nt++) {
            mxA = fmaxf(mxA, fmaxf(s[nt][0], s[nt][1]));
            mxB = fmaxf(mxB, fmaxf(s[nt][2], s[nt][3]));
        }
#pragma unroll
        for (int off = 1; off < 4; off <<= 1) {
            mxA = fmaxf(mxA, __shfl_xor_sync(0xffffffffu, mxA, off));
            mxB = fmaxf(mxB, __shfl_xor_sync(0xffffffffu, mxB, off));
        }
        float mnA = fmaxf(mA, mxA), mnB = fmaxf(mB, mxB);
        float fA = __expf(mA - mnA), fB = __expf(mB - mnB);
        mA = mnA; mB = mnB;
        float sumA = 0.0f, sumB = 0.0f;
#pragma unroll
        for (int nt = 0; nt < 8; nt++) {
            s[nt][0] = __expf(s[nt][0] - mA);
            s[nt][1] = __expf(s[nt][1] - mA);
            s[nt][2] = __expf(s[nt][2] - mB);
            s[nt][3] = __expf(s[nt][3] - mB);
            sumA += s[nt][0] + s[nt][1];
            sumB += s[nt][2] + s[nt][3];
        }
#pragma unroll
        for (int off = 1; off < 4; off <<= 1) {
            sumA += __shfl_xor_sync(0xffffffffu, sumA, off);
            sumB += __shfl_xor_sync(0xffffffffu, sumB, off);
        }
        lA = lA * fA + sumA;
        lB = lB * fB + sumB;
#pragma unroll
        for (int dt = 0; dt < 8; dt++) {
            o[dt][0] *= fA; o[dt][1] *= fA;
            o[dt][2] *= fB; o[dt][3] *= fB;
        }

        // stage P (tf32) to per-warp smem
        float* pw = Ps + w * 16 * PSTR;
#pragma unroll
        for (int nt = 0; nt < 8; nt++) {
            int c = nt * 8 + tig * 2;
            pw[gid * PSTR + c]           = tf32f(s[nt][0]);
            pw[gid * PSTR + c + 1]       = tf32f(s[nt][1]);
            pw[(gid + 8) * PSTR + c]     = tf32f(s[nt][2]);
            pw[(gid + 8) * PSTR + c + 1] = tf32f(s[nt][3]);
        }
        __syncwarp();

        // O += P V
#pragma unroll
        for (int ks = 0; ks < 8; ks++) {
            int k0 = ks * 8;
            unsigned ap[4];
            ap[0] = __float_as_uint(pw[gid * PSTR + k0 + tig]);
            ap[1] = __float_as_uint(pw[(gid + 8) * PSTR + k0 + tig]);
            ap[2] = __float_as_uint(pw[gid * PSTR + k0 + tig + 4]);
            ap[3] = __float_as_uint(pw[(gid + 8) * PSTR + k0 + tig + 4]);
#pragma unroll
            for (int dt = 0; dt < 8; dt++) {
                unsigned bv[2];
                bv[0] = __float_as_uint(Vb[(k0 + tig)     * VSTR + dt * 8 + gid]);
                bv[1] = __float_as_uint(Vb[(k0 + tig + 4) * VSTR + dt * 8 + gid]);
                mma_tf32(o[dt], ap, bv);
            }
        }
        __syncwarp();

        if (kt + 1 < NKT) {
            cp_wait0();        // next tile resident
            __syncthreads();   // all warps done reading current buffers
        }
    }

    // finalize
    float invA = 1.0f / lA, invB = 1.0f / lB;
    long rowA = (long)(b * SEQ + q0 + w * 16 + gid) * EMB;
    long rowB = rowA + 8L * EMB;
#pragma unroll
    for (int dt = 0; dt < 8; dt++) {
        int gn = h * HD + dt * 8 + tig * 2;
        *(float2*)(ctx + rowA + gn) = make_float2(o[dt][0] * invA, o[dt][1] * invA);
        *(float2*)(ctx + rowB + gn) = make_float2(o[dt][2] * invB, o[dt][3] * invB);
    }
}

// ---------------- launch ----------------------------------------------------
extern "C" void kernel_launch(void* const* d_in, const int* in_sizes, int n_in,
                              void* d_out, int out_size)
{
    const float* x    = (const float*)d_in[0];
    const int*   mask = (const int*)  d_in[1];
    const float* Wq   = (const float*)d_in[2];
    const float* bq   = (const float*)d_in[3];
    const float* Wk   = (const float*)d_in[4];
    const float* bk   = (const float*)d_in[5];
    const float* Wv   = (const float*)d_in[6];
    const float* bv   = (const float*)d_in[7];
    const float* Wo   = (const float*)d_in[8];
    const float* bo   = (const float*)d_in[9];
    float* out = (float*)d_out;

    float *pWq, *pWk, *pWv, *pWo, *pQ, *pK, *pV, *pCtx;
    int* pMsum;
    cudaGetSymbolAddress((void**)&pWq, g_Wq);
    cudaGetSymbolAddress((void**)&pWk, g_Wk);
    cudaGetSymbolAddress((void**)&pWv, g_Wv);
    cudaGetSymbolAddress((void**)&pWo, g_Wo);
    cudaGetSymbolAddress((void**)&pQ,  g_Q);
    cudaGetSymbolAddress((void**)&pK,  g_K);
    cudaGetSymbolAddress((void**)&pV,  g_V);
    cudaGetSymbolAddress((void**)&pCtx, g_ctx);
    cudaGetSymbolAddress((void**)&pMsum, g_msum);

    const int gemm_smem  = (2*128*ASTR + 2*32*BSTR) * (int)sizeof(float);   // ~70KB
    const int flash_smem = (BQ*QSTR + 2*BKV*KSTR + 2*BKV*VSTR + 8*16*PSTR) * (int)sizeof(float); // ~140KB
    cudaFuncSetAttribute(gemm_tf32, cudaFuncAttributeMaxDynamicSharedMemorySize, gemm_smem);
    cudaFuncSetAttribute(flash_tf32, cudaFuncAttributeMaxDynamicSharedMemorySize, flash_smem);

    // 1. expand quaternion weights (single launch) + mask tile summary
    Exp4 e;
    e.W[0] = Wq; e.W[1] = Wk; e.W[2] = Wv; e.W[3] = Wo;
    e.Wb[0] = pWq; e.Wb[1] = pWk; e.Wb[2] = pWv; e.Wb[3] = pWo;
    expand4_kernel<<<dim3(NBQ*NBQ/256, 4), 256>>>(e);
    mask_summary<<<NQT*NKT, 256>>>(mask, pMsum);

    // 2. fused Q/K/V projections (outputs tf32-rounded; Q pre-scaled by 1/8)
    GemmArgs qkv;
    qkv.A = x;
    qkv.W[0] = pWq; qkv.W[1] = pWk; qkv.W[2] = pWv;
    qkv.bias[0] = bq; qkv.bias[1] = bk; qkv.bias[2] = bv;
    qkv.out[0] = pQ; qkv.out[1] = pK; qkv.out[2] = pV;
    qkv.oscale[0] = 0.125f; qkv.oscale[1] = 1.0f; qkv.oscale[2] = 1.0f;
    qkv.round_out = 1;
    dim3 ggrid(EMB/128, NROWS/128, 3);
    gemm_tf32<<<ggrid, 256, gemm_smem>>>(qkv);

    // 3. attention
    dim3 agrid(SEQ/BQ, NH, NBATCH);
    flash_tf32<<<agrid, 256, flash_smem>>>(pQ, pK, pV, mask, pMsum, pCtx);

    // 4. output projection -> d_out (fp32 output, no rounding)
    GemmArgs og;
    og.A = pCtx;
    og.W[0] = pWo; og.W[1] = pWo; og.W[2] = pWo;
    og.bias[0] = bo; og.bias[1] = bo; og.bias[2] = bo;
    og.out[0] = out; og.out[1] = out; og.out[2] = out;
    og.oscale[0] = 1.0f; og.oscale[1] = 1.0f; og.oscale[2] = 1.0f;
    og.round_out = 0;
    dim3 ogrid(EMB/128, NROWS/128, 1);
    gemm_tf32<<<ogrid, 256, gemm_smem>>>(og);
}

// round 5
// speedup vs baseline: 1.0701x; 1.0701x over previous
#include <cuda_runtime.h>
#include <cstdint>
#include <math.h>

#define SEQ 2048
#define EMB 1024
#define NBQ 256
#define NH 16
#define HD 64
#define NBATCH 2
#define NROWS (NBATCH*SEQ)   // 4096
#define NKT (SEQ/64)         // 32 kv tiles
#define NQT (SEQ/128)        // 16 q tiles

// ---------------- scratch (device globals) ---------------------------------
__device__ float g_Wq[EMB*EMB];
__device__ float g_Wk[EMB*EMB];
__device__ float g_Wv[EMB*EMB];
__device__ float g_Wo[EMB*EMB];
__device__ float g_Q[NROWS*EMB];
__device__ float g_K[NROWS*EMB];
__device__ float g_V[NROWS*EMB];
__device__ float g_ctx[NROWS*EMB];
__device__ int   g_msum[NQT*NKT];

// ---------------- helpers ---------------------------------------------------
__device__ __forceinline__ unsigned f2tf32(float x) {
    unsigned u;
    asm("cvt.rna.tf32.f32 %0, %1;" : "=r"(u) : "f"(x));
    return u;
}
__device__ __forceinline__ float tf32f(float x) { return __uint_as_float(f2tf32(x)); }

__device__ __forceinline__ void mma_tf32(float* d, const unsigned* a, const unsigned* b) {
    asm volatile(
        "mma.sync.aligned.m16n8k8.row.col.f32.tf32.tf32.f32 "
        "{%0,%1,%2,%3},{%4,%5,%6,%7},{%8,%9},{%0,%1,%2,%3};"
        : "+f"(d[0]), "+f"(d[1]), "+f"(d[2]), "+f"(d[3])
        : "r"(a[0]), "r"(a[1]), "r"(a[2]), "r"(a[3]), "r"(b[0]), "r"(b[1]));
}

__device__ __forceinline__ uint32_t sa(const void* p) {
    return (uint32_t)__cvta_generic_to_shared(p);
}
__device__ __forceinline__ void cpa16(uint32_t s, const void* g) {
    asm volatile("cp.async.cg.shared.global [%0], [%1], 16;" :: "r"(s), "l"(g));
}
__device__ __forceinline__ void cp_commit() {
    asm volatile("cp.async.commit_group;" ::: "memory");
}
__device__ __forceinline__ void cp_wait0() {
    asm volatile("cp.async.wait_group 0;" ::: "memory");
}

// ---------------- weight expansion (quaternion left-mult), 4-in-1 ----------
struct Exp4 { const float* W[4]; float* Wb[4]; };

__global__ void expand4_kernel(Exp4 e) {
    int z = blockIdx.y;
    int idx = blockIdx.x * blockDim.x + threadIdx.x;
    if (idx >= NBQ * NBQ) return;
    int o = idx / NBQ;
    int n = idx % NBQ;
    const float* w = e.W[z] + (o * NBQ + n) * 4;
    float w0 = tf32f(w[0]), w1 = tf32f(w[1]), w2 = tf32f(w[2]), w3 = tf32f(w[3]);
    float* base = e.Wb[z] + (n * 4) * EMB + o * 4;
    *(float4*)(base + 0 * EMB) = make_float4( w0,  w1,  w2,  w3);
    *(float4*)(base + 1 * EMB) = make_float4(-w1,  w0,  w3, -w2);
    *(float4*)(base + 2 * EMB) = make_float4(-w2, -w3,  w0,  w1);
    *(float4*)(base + 3 * EMB) = make_float4(-w3,  w2, -w1,  w0);
}

// ---------------- mask tile summary (128q x 64k tiles) ----------------------
__global__ void mask_summary(const int* __restrict__ mask, int* __restrict__ sum) {
    int tile = blockIdx.x;
    int qt = tile / NKT, kt = tile % NKT;
    int tid = threadIdx.x;
    int ok = 1;
    for (int i = tid; i < 128*64; i += 256) {
        int r = i / 64, c = i % 64;
        ok &= (mask[(qt*128 + r) * SEQ + kt*64 + c] != 0);
    }
    int allok = __syncthreads_and(ok);
    if (tid == 0) sum[tile] = allok;
}

// ---------------- TF32 tensor-core GEMM (double-buffered) -------------------
#define ASTR 36
#define BSTR 136

struct GemmArgs {
    const float* A;
    const float* W[3];
    const float* bias[3];
    float* out[3];
    float oscale[3];
    int round_out;
};

__global__ __launch_bounds__(256) void gemm_tf32(GemmArgs ga) {
    extern __shared__ float gs[];
    float* Asm = gs;                       // 2 * 128*ASTR
    float* Bsm = gs + 2 * 128 * ASTR;      // 2 * 32*BSTR

    int tid = threadIdx.x;
    int z = blockIdx.z;
    const float* A = ga.A;
    const float* W = ga.W[z];
    const float* bias = ga.bias[z];
    float* C = ga.out[z];

    int bm = blockIdx.y * 128;
    int bn = blockIdx.x * 128;
    int warp = tid / 32, lane = tid % 32;
    int gid = lane >> 2, tig = lane & 3;
    int wm = (warp / 4) * 64, wn = (warp % 4) * 32;

    int arow = tid / 8;
    int acol = (tid % 8) * 4;
    int brow = tid / 32;
    int bcol = (tid % 32) * 4;

    float acc[4][4][4];
#pragma unroll
    for (int mt = 0; mt < 4; mt++)
#pragma unroll
        for (int nt = 0; nt < 4; nt++)
#pragma unroll
            for (int r = 0; r < 4; r++) acc[mt][nt][r] = 0.0f;

    float4 pa[4], pb[4];

#define LOADG(k0)                                                              \
    {                                                                          \
        _Pragma("unroll")                                                      \
        for (int i = 0; i < 4; i++)                                            \
            pa[i] = *(const float4*)(A + (long)(bm + arow + i*32) * EMB + (k0) + acol); \
        _Pragma("unroll")                                                      \
        for (int i = 0; i < 4; i++)                                            \
            pb[i] = *(const float4*)(W + (long)((k0) + brow + i*8) * EMB + bn + bcol);  \
    }
#define STORES(asb, bsb)                                                       \
    {                                                                          \
        _Pragma("unroll")                                                      \
        for (int i = 0; i < 4; i++) {                                          \
            int r = arow + i*32;                                               \
            (asb)[r*ASTR + acol + 0] = tf32f(pa[i].x);                         \
            (asb)[r*ASTR + acol + 1] = tf32f(pa[i].y);                         \
            (asb)[r*ASTR + acol + 2] = tf32f(pa[i].z);                         \
            (asb)[r*ASTR + acol + 3] = tf32f(pa[i].w);                         \
        }                                                                      \
        _Pragma("unroll")                                                      \
        for (int i = 0; i < 4; i++) {                                          \
            int r = brow + i*8;                                                \
            (bsb)[r*BSTR + bcol + 0] = tf32f(pb[i].x);                         \
            (bsb)[r*BSTR + bcol + 1] = tf32f(pb[i].y);                         \
            (bsb)[r*BSTR + bcol + 2] = tf32f(pb[i].z);                         \
            (bsb)[r*BSTR + bcol + 3] = tf32f(pb[i].w);                         \
        }                                                                      \
    }

    LOADG(0);
    STORES(Asm, Bsm);
    __syncthreads();

    for (int kt = 0; kt < EMB / 32; kt++) {
        if (kt + 1 < EMB / 32) LOADG((kt + 1) * 32);

        const float* As = Asm + (kt & 1) * 128 * ASTR;
        const float* Bs = Bsm + (kt & 1) * 32 * BSTR;
#pragma unroll
        for (int ks = 0; ks < 4; ks++) {
            int k0 = ks * 8;
            unsigned af[4][4], bf[4][2];
#pragma unroll
            for (int mt = 0; mt < 4; mt++) {
                int r0 = wm + mt * 16;
                af[mt][0] = __float_as_uint(As[(r0 + gid)     * ASTR + k0 + tig]);
                af[mt][1] = __float_as_uint(As[(r0 + gid + 8) * ASTR + k0 + tig]);
                af[mt][2] = __float_as_uint(As[(r0 + gid)     * ASTR + k0 + tig + 4]);
                af[mt][3] = __float_as_uint(As[(r0 + gid + 8) * ASTR + k0 + tig + 4]);
            }
#pragma unroll
            for (int nt = 0; nt < 4; nt++) {
                int c0 = wn + nt * 8;
                bf[nt][0] = __float_as_uint(Bs[(k0 + tig)     * BSTR + c0 + gid]);
                bf[nt][1] = __float_as_uint(Bs[(k0 + tig + 4) * BSTR + c0 + gid]);
            }
#pragma unroll
            for (int mt = 0; mt < 4; mt++)
#pragma unroll
                for (int nt = 0; nt < 4; nt++)
                    mma_tf32(acc[mt][nt], af[mt], bf[nt]);
        }
        if (kt + 1 < EMB / 32) {
            STORES(Asm + ((kt + 1) & 1) * 128 * ASTR,
                   Bsm + ((kt + 1) & 1) * 32 * BSTR);
            __syncthreads();
        }
    }

    float os = ga.oscale[z];
    int rnd = ga.round_out;
#pragma unroll
    for (int mt = 0; mt < 4; mt++)
#pragma unroll
        for (int nt = 0; nt < 4; nt++) {
            int gm = bm + wm + mt * 16 + gid;
            int gn = bn + wn + nt * 8 + tig * 2;
            float b0 = bias[gn], b1 = bias[gn + 1];
            float v0 = (acc[mt][nt][0] + b0) * os;
            float v1 = (acc[mt][nt][1] + b1) * os;
            float v2 = (acc[mt][nt][2] + b0) * os;
            float v3 = (acc[mt][nt][3] + b1) * os;
            if (rnd) { v0 = tf32f(v0); v1 = tf32f(v1); v2 = tf32f(v2); v3 = tf32f(v3); }
            *(float2*)(C + (long)gm * EMB + gn) = make_float2(v0, v1);
            *(float2*)(C + (long)(gm + 8) * EMB + gn) = make_float2(v2, v3);
        }
}

// ---------------- TF32 flash attention (BQ=128, reg-shuffled P, 2 CTA/SM) ---
#define BQ 128
#define BKV 64
#define QSTR 68
#define KSTR 68
#define VSTR 72

__global__ __launch_bounds__(256, 2) void flash_tf32(
    const float* __restrict__ Q, const float* __restrict__ K,
    const float* __restrict__ V, const int* __restrict__ mask,
    const int* __restrict__ msum, float* __restrict__ ctx)
{
    extern __shared__ float fs[];
    float* Qs = fs;                         // BQ*QSTR       = 8704 f
    float* Ks = Qs + BQ * QSTR;             // 2*BKV*KSTR    = 8704 f
    float* Vs = Ks + 2 * BKV * KSTR;        // 2*BKV*VSTR    = 9216 f
                                            // total ~104 KB -> 2 CTAs/SM

    int tid = threadIdx.x;
    int w = tid / 32, lane = tid % 32;
    int gid = lane >> 2, tig = lane & 3;
    int qt = blockIdx.x, h = blockIdx.y, b = blockIdx.z;
    int q0 = qt * BQ;

    // Q tile via cp.async (already tf32-rounded + pre-scaled by GEMM epilogue)
    {
        int row = tid >> 1;
        int c0 = (tid & 1) * 32;
        const float* g = Q + (long)(b * SEQ + q0 + row) * EMB + h * HD + c0;
        uint32_t s = sa(Qs + row * QSTR + c0);
#pragma unroll
        for (int j = 0; j < 8; j++) cpa16(s + j * 16, g + j * 4);
    }
    // K/V tile 0 into buffer 0
    {
        int row = tid >> 2;
        int c0 = (tid & 3) * 16;
        long gr = (long)(b * SEQ + row) * EMB + h * HD + c0;
        uint32_t ks = sa(Ks + row * KSTR + c0);
        uint32_t vs = sa(Vs + row * VSTR + c0);
#pragma unroll
        for (int j = 0; j < 4; j++) cpa16(ks + j * 16, K + gr + j * 4);
#pragma unroll
        for (int j = 0; j < 4; j++) cpa16(vs + j * 16, V + gr + j * 4);
    }
    cp_commit();
    cp_wait0();
    __syncthreads();

    // hoist Q fragments
    unsigned aq[8][4];
#pragma unroll
    for (int ks = 0; ks < 8; ks++) {
        int r0 = w * 16;
        int k0 = ks * 8;
        aq[ks][0] = __float_as_uint(Qs[(r0 + gid)     * QSTR + k0 + tig]);
        aq[ks][1] = __float_as_uint(Qs[(r0 + gid + 8) * QSTR + k0 + tig]);
        aq[ks][2] = __float_as_uint(Qs[(r0 + gid)     * QSTR + k0 + tig + 4]);
        aq[ks][3] = __float_as_uint(Qs[(r0 + gid + 8) * QSTR + k0 + tig + 4]);
    }

    float o[8][4];
#pragma unroll
    for (int dt = 0; dt < 8; dt++)
#pragma unroll
        for (int r = 0; r < 4; r++) o[dt][r] = 0.0f;
    float mA = -1e30f, mB = -1e30f, lA = 0.0f, lB = 0.0f;

    const int src_lo = (lane & ~3) | (tig >> 1);
    const int src_hi = src_lo + 2;
    const bool odd = (tig & 1);

    for (int kt = 0; kt < NKT; kt++) {
        // prefetch next K/V tile into the other buffer
        if (kt + 1 < NKT) {
            int nb = (kt + 1) & 1;
            int row = tid >> 2;
            int c0 = (tid & 3) * 16;
            long gr = (long)(b * SEQ + (kt + 1) * BKV + row) * EMB + h * HD + c0;
            uint32_t ks = sa(Ks + nb * BKV * KSTR + row * KSTR + c0);
            uint32_t vs = sa(Vs + nb * BKV * VSTR + row * VSTR + c0);
#pragma unroll
            for (int j = 0; j < 4; j++) cpa16(ks + j * 16, K + gr + j * 4);
#pragma unroll
            for (int j = 0; j < 4; j++) cpa16(vs + j * 16, V + gr + j * 4);
            cp_commit();
        }

        const float* Kb = Ks + (kt & 1) * BKV * KSTR;
        const float* Vb = Vs + (kt & 1) * BKV * VSTR;

        // S = Q K^T
        float s[8][4];
#pragma unroll
        for (int nt = 0; nt < 8; nt++) {
            s[nt][0] = s[nt][1] = s[nt][2] = s[nt][3] = 0.0f;
#pragma unroll
            for (int ks = 0; ks < 8; ks++) {
                int k0 = ks * 8;
                unsigned bk[2];
                bk[0] = __float_as_uint(Kb[(nt * 8 + gid) * KSTR + k0 + tig]);
                bk[1] = __float_as_uint(Kb[(nt * 8 + gid) * KSTR + k0 + tig + 4]);
                mma_tf32(s[nt], aq[ks], bk);
            }
        }

        // mask (only when tile contains zeros)
        if (!msum[qt * NKT + kt]) {
            int qrA = q0 + w * 16 + gid;
            int qrB = qrA + 8;
#pragma unroll
            for (int nt = 0; nt < 8; nt++) {
                int kc = kt * 64 + nt * 8 + tig * 2;
                const int* mpA = mask + (long)qrA * SEQ + kc;
                const int* mpB = mask + (long)qrB * SEQ + kc;
                if (mpA[0] == 0) s[nt][0] = -1e30f;
                if (mpA[1] == 0) s[nt][1] = -1e30f;
                if (mpB[0] == 0) s[nt][2] = -1e30f;
                if (mpB[1] == 0) s[nt][3] = -1e30f;
            }
        }

        // online softmax (rows gid / gid+8)
        float mxA = -1e30f, mxB = -1e30f;
#pragma unroll
        for (int nt = 0; nt < 8; nt++) {
            mxA = fmaxf(mxA, fmaxf(s[nt][0], s[nt][1]));
            mxB = fmaxf(mxB, fmaxf(s[nt][2], s[nt][3]));
        }
#pragma unroll
        for (int off = 1; off < 4; off <<= 1) {
            mxA = fmaxf(mxA, __shfl_xor_sync(0xffffffffu, mxA, off));
            mxB = fmaxf(mxB, __shfl_xor_sync(0xffffffffu, mxB, off));
        }
        float mnA = fmaxf(mA, mxA), mnB = fmaxf(mB, mxB);
        float fA = __expf(mA - mnA), fB = __expf(mB - mnB);
        mA = mnA; mB = mnB;
        float sumA = 0.0f, sumB = 0.0f;
#pragma unroll
        for (int nt = 0; nt < 8; nt++) {
            s[nt][0] = __expf(s[nt][0] - mA);
            s[nt][1] = __expf(s[nt][1] - mA);
            s[nt][2] = __expf(s[nt][2] - mB);
            s[nt][3] = __expf(s[nt][3] - mB);
            sumA += s[nt][0] + s[nt][1];
            sumB += s[nt][2] + s[nt][3];
        }
#pragma unroll
        for (int off = 1; off < 4; off <<= 1) {
            sumA += __shfl_xor_sync(0xffffffffu, sumA, off);
            sumB += __shfl_xor_sync(0xffffffffu, sumB, off);
        }
        lA = lA * fA + sumA;
        lB = lB * fB + sumB;
#pragma unroll
        for (int dt = 0; dt < 8; dt++) {
            o[dt][0] *= fA; o[dt][1] *= fA;
            o[dt][2] *= fB; o[dt][3] *= fB;
        }

        // tf32-round P in registers
        unsigned up[8][4];
#pragma unroll
        for (int nt = 0; nt < 8; nt++) {
            up[nt][0] = f2tf32(s[nt][0]);
            up[nt][1] = f2tf32(s[nt][1]);
            up[nt][2] = f2tf32(s[nt][2]);
            up[nt][3] = f2tf32(s[nt][3]);
        }

        // O += P V  (A-fragment of P built via quad shuffles — no smem staging)
        // S-accum layout: lane(tig) holds cols {2tig, 2tig+1}; A-frag needs
        // cols {tig, tig+4}: col c lives on quad-lane c>>1, slot c&1.
#pragma unroll
        for (int ks = 0; ks < 8; ks++) {
            unsigned e0 = __shfl_sync(0xffffffffu, up[ks][0], src_lo);
            unsigned o0 = __shfl_sync(0xffffffffu, up[ks][1], src_lo);
            unsigned e1 = __shfl_sync(0xffffffffu, up[ks][2], src_lo);
            unsigned o1 = __shfl_sync(0xffffffffu, up[ks][3], src_lo);
            unsigned e2 = __shfl_sync(0xffffffffu, up[ks][0], src_hi);
            unsigned o2 = __shfl_sync(0xffffffffu, up[ks][1], src_hi);
            unsigned e3 = __shfl_sync(0xffffffffu, up[ks][2], src_hi);
            unsigned o3 = __shfl_sync(0xffffffffu, up[ks][3], src_hi);
            unsigned ap[4];
            ap[0] = odd ? o0 : e0;   // P[gid][tig]
            ap[1] = odd ? o1 : e1;   // P[gid+8][tig]
            ap[2] = odd ? o2 : e2;   // P[gid][tig+4]
            ap[3] = odd ? o3 : e3;   // P[gid+8][tig+4]
            int k0 = ks * 8;
#pragma unroll
            for (int dt = 0; dt < 8; dt++) {
                unsigned bv[2];
                bv[0] = __float_as_uint(Vb[(k0 + tig)     * VSTR + dt * 8 + gid]);
                bv[1] = __float_as_uint(Vb[(k0 + tig + 4) * VSTR + dt * 8 + gid]);
                mma_tf32(o[dt], ap, bv);
            }
        }

        if (kt + 1 < NKT) {
            cp_wait0();        // next tile resident
            __syncthreads();   // all warps done reading current buffers
        }
    }

    // finalize
    float invA = 1.0f / lA, invB = 1.0f / lB;
    long rowA = (long)(b * SEQ + q0 + w * 16 + gid) * EMB;
    long rowB = rowA + 8L * EMB;
#pragma unroll
    for (int dt = 0; dt < 8; dt++) {
        int gn = h * HD + dt * 8 + tig * 2;
        *(float2*)(ctx + rowA + gn) = make_float2(o[dt][0] * invA, o[dt][1] * invA);
        *(float2*)(ctx + rowB + gn) = make_float2(o[dt][2] * invB, o[dt][3] * invB);
    }
}

// ---------------- launch ----------------------------------------------------
extern "C" void kernel_launch(void* const* d_in, const int* in_sizes, int n_in,
                              void* d_out, int out_size)
{
    const float* x    = (const float*)d_in[0];
    const int*   mask = (const int*)  d_in[1];
    const float* Wq   = (const float*)d_in[2];
    const float* bq   = (const float*)d_in[3];
    const float* Wk   = (const float*)d_in[4];
    const float* bk   = (const float*)d_in[5];
    const float* Wv   = (const float*)d_in[6];
    const float* bv   = (const float*)d_in[7];
    const float* Wo   = (const float*)d_in[8];
    const float* bo   = (const float*)d_in[9];
    float* out = (float*)d_out;

    float *pWq, *pWk, *pWv, *pWo, *pQ, *pK, *pV, *pCtx;
    int* pMsum;
    cudaGetSymbolAddress((void**)&pWq, g_Wq);
    cudaGetSymbolAddress((void**)&pWk, g_Wk);
    cudaGetSymbolAddress((void**)&pWv, g_Wv);
    cudaGetSymbolAddress((void**)&pWo, g_Wo);
    cudaGetSymbolAddress((void**)&pQ,  g_Q);
    cudaGetSymbolAddress((void**)&pK,  g_K);
    cudaGetSymbolAddress((void**)&pV,  g_V);
    cudaGetSymbolAddress((void**)&pCtx, g_ctx);
    cudaGetSymbolAddress((void**)&pMsum, g_msum);

    const int gemm_smem  = (2*128*ASTR + 2*32*BSTR) * (int)sizeof(float);   // ~70KB
    const int flash_smem = (BQ*QSTR + 2*BKV*KSTR + 2*BKV*VSTR) * (int)sizeof(float); // ~104KB
    cudaFuncSetAttribute(gemm_tf32, cudaFuncAttributeMaxDynamicSharedMemorySize, gemm_smem);
    cudaFuncSetAttribute(flash_tf32, cudaFuncAttributeMaxDynamicSharedMemorySize, flash_smem);

    // 1. expand quaternion weights (single launch) + mask tile summary
    Exp4 e;
    e.W[0] = Wq; e.W[1] = Wk; e.W[2] = Wv; e.W[3] = Wo;
    e.Wb[0] = pWq; e.Wb[1] = pWk; e.Wb[2] = pWv; e.Wb[3] = pWo;
    expand4_kernel<<<dim3(NBQ*NBQ/256, 4), 256>>>(e);
    mask_summary<<<NQT*NKT, 256>>>(mask, pMsum);

    // 2. fused Q/K/V projections (outputs tf32-rounded; Q pre-scaled by 1/8)
    GemmArgs qkv;
    qkv.A = x;
    qkv.W[0] = pWq; qkv.W[1] = pWk; qkv.W[2] = pWv;
    qkv.bias[0] = bq; qkv.bias[1] = bk; qkv.bias[2] = bv;
    qkv.out[0] = pQ; qkv.out[1] = pK; qkv.out[2] = pV;
    qkv.oscale[0] = 0.125f; qkv.oscale[1] = 1.0f; qkv.oscale[2] = 1.0f;
    qkv.round_out = 1;
    dim3 ggrid(EMB/128, NROWS/128, 3);
    gemm_tf32<<<ggrid, 256, gemm_smem>>>(qkv);

    // 3. attention
    dim3 agrid(SEQ/BQ, NH, NBATCH);
    flash_tf32<<<agrid, 256, flash_smem>>>(pQ, pK, pV, mask, pMsum, pCtx);

    // 4. output projection -> d_out (fp32 output, no rounding)
    GemmArgs og;
    og.A = pCtx;
    og.W[0] = pWo; og.W[1] = pWo; og.W[2] = pWo;
    og.bias[0] = bo; og.bias[1] = bo; og.bias[2] = bo;
    og.out[0] = out; og.out[1] = out; og.out[2] = out;
    og.oscale[0] = 1.0f; og.oscale[1] = 1.0f; og.oscale[2] = 1.0f;
    og.round_out = 0;
    dim3 ogrid(EMB/128, NROWS/128, 1);
    gemm_tf32<<<ogrid, 256, gemm_smem>>>(og);
}